// round 17
// baseline (speedup 1.0000x reference)
#include <cuda_runtime.h>
#include <cuda_bf16.h>
#include <mma.h>
#include <cstdint>

// Attention_2362232013200 — B=256, S=196, D=2048, H=512, all fp32.
// R17: k1 GEMM on WMMA bf16 (base-ISA tensor path; tcgen05 is unavailable —
//      harness compiles PTX at compute_103 without the 'a' feature set).
//      3-term hi/lo split, K'=6144 concat. k2/k4 = proven R11 versions.

using namespace nvcuda;

constexpr int B = 256;
constexpr int S = 196;
constexpr int D = 2048;
constexpr int H = 512;
constexpr int KSM = 8;            // split-K for the MMA GEMM
constexpr int KP = 3 * D;         // 6144 concatenated K
constexpr int KCB = KP / KSM;     // 768 K per block
constexpr int BKs = 32;           // K per stage
constexpr int NST = KCB / BKs;    // 24 stages

// ---- scratch (device globals; no allocations allowed) ----
__device__ __align__(16) __nv_bfloat16 g_aconv[B * KP];   // [256][6144] row-major
__device__ __align__(16) __nv_bfloat16 g_bconv[H * KP];   // [512][6144] row-major
__device__ __align__(16) float g_part[KSM * B * H];       // 4 MB split-K partials
__device__ __align__(16) float g_weight[B * S];

__device__ __forceinline__ float tanh_approx(float x) {
    float r; asm("tanh.approx.f32 %0, %1;" : "=f"(r) : "f"(x)); return r;
}

// ---------------------------------------------------------------------------
// K0: build bf16 operands (both row-major, ld = KP).
//   A' seg layout over kc: [0,2048) hi(h) | [2048,4096) lo(h) | [4096,6144) hi(h)
//   B' seg layout over kc: [0,2048) hi(W) | [2048,4096) hi(W) | [4096,6144) lo(W)
//   => products: hi·hi + lo·hi + hi·lo  (misses lo·lo ~ 2^-16 rel)
// Grid: 768 blocks for A', then 1536 for B'; 256 thr; 1 uint4 (8 bf16) each.
// ---------------------------------------------------------------------------
__global__ __launch_bounds__(256) void k0_convert(const float* __restrict__ h,
                                                  const float* __restrict__ W) {
    const int g = blockIdx.x * 256 + threadIdx.x;
    __nv_bfloat16 o[8];
    if (blockIdx.x < 768) {
        const int m = g / 768;                 // row 0..255
        const int kc0 = (g % 768) * 8;
        const int seg = kc0 >> 11;
        const float* src = h + (size_t)m * D + (kc0 & 2047);
#pragma unroll
        for (int j = 0; j < 8; ++j) {
            float x = src[j];
            __nv_bfloat16 hi = __float2bfloat16(x);
            o[j] = (seg == 1) ? __float2bfloat16(x - __bfloat162float(hi)) : hi;
        }
        ((uint4*)g_aconv)[g] = *(const uint4*)o;
    } else {
        const int idx = g - 768 * 256;
        const int n = idx / 768;               // row 0..511
        const int kc0 = (idx % 768) * 8;
        const int seg = kc0 >> 11;
        const float* src = W + (size_t)n * D + (kc0 & 2047);
#pragma unroll
        for (int j = 0; j < 8; ++j) {
            float x = src[j];
            __nv_bfloat16 hi = __float2bfloat16(x);
            o[j] = (seg == 2) ? __float2bfloat16(x - __bfloat162float(hi)) : hi;
        }
        ((uint4*)g_bconv)[idx] = *(const uint4*)o;
    }
}

// ---------------------------------------------------------------------------
// K1: WMMA bf16 split-K GEMM. part[z][m][n] = sum_{k in z-chunk} A'[m,k]B'[n,k]
// BM=128, BN=64, BK=32. 256 threads = 8 warps in 4(m) x 2(n); warp tile 32x32
// = 2x2 wmma 16x16x16 frags, fp32 accum. Grid (2, 8, KSM) = 128 blocks.
// A row-major; B loaded as col-major fragment (W is [n][k] => (k,n) at n*ld+k).
// ---------------------------------------------------------------------------
__global__ __launch_bounds__(256) void k1_wmma() {
    __shared__ __align__(16) __nv_bfloat16 As[128][40];   // ld=40 (pad)
    __shared__ __align__(16) __nv_bfloat16 Bs[64][40];

    const int tid = threadIdx.x;
    const int wid = tid >> 5;
    const int bm = blockIdx.x * 128;
    const int bn = blockIdx.y * 64;
    const int k0 = blockIdx.z * KCB;

    const int wm = (wid >> 1) * 32;           // warp m offset in tile
    const int wn = (wid & 1) * 32;            // warp n offset in tile

    // A loader: 512 uint4 chunks; chunk c: row c>>2, col (c&3)*8. Two per thread.
    const int ar0 = tid >> 2;                 // rows tid>>2 and (tid+256)>>2
    const int ac0 = (tid & 3) * 8;
    // B loader: 256 chunks; row tid>>2, col (tid&3)*8.
    const int br = tid >> 2;

    wmma::fragment<wmma::accumulator, 16, 16, 16, float> cf[2][2];
#pragma unroll
    for (int i = 0; i < 2; ++i)
#pragma unroll
        for (int j = 0; j < 2; ++j) wmma::fill_fragment(cf[i][j], 0.0f);

    for (int st = 0; st < NST; ++st) {
        const int ks = k0 + st * BKs;
        uint4 a0 = *(const uint4*)(g_aconv + (size_t)(bm + ar0) * KP + ks + ac0);
        uint4 a1 = *(const uint4*)(g_aconv + (size_t)(bm + ar0 + 64) * KP + ks + ac0);
        uint4 b0 = *(const uint4*)(g_bconv + (size_t)(bn + br) * KP + ks + ac0);
        if (st) __syncthreads();
        *(uint4*)&As[ar0][ac0]      = a0;
        *(uint4*)&As[ar0 + 64][ac0] = a1;
        *(uint4*)&Bs[br][ac0]       = b0;
        __syncthreads();

#pragma unroll
        for (int kk = 0; kk < BKs; kk += 16) {
            wmma::fragment<wmma::matrix_a, 16, 16, 16, __nv_bfloat16,
                           wmma::row_major> af[2];
            wmma::fragment<wmma::matrix_b, 16, 16, 16, __nv_bfloat16,
                           wmma::col_major> bf[2];
#pragma unroll
            for (int i = 0; i < 2; ++i)
                wmma::load_matrix_sync(af[i], &As[wm + i * 16][kk], 40);
#pragma unroll
            for (int j = 0; j < 2; ++j)
                wmma::load_matrix_sync(bf[j], &Bs[wn + j * 16][kk], 40);
#pragma unroll
            for (int i = 0; i < 2; ++i)
#pragma unroll
                for (int j = 0; j < 2; ++j)
                    wmma::mma_sync(cf[i][j], af[i], bf[j], cf[i][j]);
        }
    }

    float* po = g_part + (size_t)blockIdx.z * (B * H);
#pragma unroll
    for (int i = 0; i < 2; ++i)
#pragma unroll
        for (int j = 0; j < 2; ++j)
            wmma::store_matrix_sync(
                po + (size_t)(bm + wm + i * 16) * H + bn + wn + j * 16,
                cf[i][j], H, wmma::mem_row_major);
}

// ---------------------------------------------------------------------------
// K2: fused split-K reduce + scores + softmax + mask renorm. One block per b.
// ---------------------------------------------------------------------------
__global__ __launch_bounds__(256) void k2_fused(const float* __restrict__ p_att,
                                                const float* __restrict__ w_alpha,
                                                const float* __restrict__ bias,
                                                const float* __restrict__ mask) {
    __shared__ __align__(16) float ah[H];
    __shared__ __align__(16) float wa[H];
    __shared__ float sc[256];
    __shared__ float red[256];

    const int b = blockIdx.x;
    const int tid = threadIdx.x;

    for (int i = tid; i < H; i += 256) {
        float s = bias[i];
#pragma unroll
        for (int z = 0; z < KSM; ++z) s += g_part[(size_t)z * (B * H) + b * H + i];
        ah[i] = s;
        wa[i] = w_alpha[i];
    }
    if (tid >= S) sc[tid] = -1e30f;
    __syncthreads();

    const int w = tid >> 5, l = tid & 31;

    for (int s = w; s < 98; s += 8) {
        const float4* pp0 = (const float4*)(p_att + (size_t)(b * S + s) * H);
        const float4* pp1 = (const float4*)(p_att + (size_t)(b * S + s + 98) * H);
        float acc0 = 0.f, acc1 = 0.f;
#pragma unroll
        for (int j = 0; j < 4; ++j) {
            const int hi = j * 32 + l;
            float4 p0 = pp0[hi];
            float4 p1 = pp1[hi];
            float4 a4 = *(const float4*)&ah[hi * 4];
            float4 w4 = *(const float4*)&wa[hi * 4];
            acc0 += w4.x * tanh_approx(p0.x + a4.x);
            acc0 += w4.y * tanh_approx(p0.y + a4.y);
            acc0 += w4.z * tanh_approx(p0.z + a4.z);
            acc0 += w4.w * tanh_approx(p0.w + a4.w);
            acc1 += w4.x * tanh_approx(p1.x + a4.x);
            acc1 += w4.y * tanh_approx(p1.y + a4.y);
            acc1 += w4.z * tanh_approx(p1.z + a4.z);
            acc1 += w4.w * tanh_approx(p1.w + a4.w);
        }
#pragma unroll
        for (int o = 16; o; o >>= 1) {
            acc0 += __shfl_xor_sync(0xFFFFFFFFu, acc0, o);
            acc1 += __shfl_xor_sync(0xFFFFFFFFu, acc1, o);
        }
        if (l == 0) { sc[s] = acc0; sc[s + 98] = acc1; }
    }
    __syncthreads();

    red[tid] = sc[tid]; __syncthreads();
    for (int o = 128; o; o >>= 1) {
        if (tid < o) red[tid] = fmaxf(red[tid], red[tid + o]);
        __syncthreads();
    }
    const float mx = red[0]; __syncthreads();

    float wgt = (tid < S) ? __expf(sc[tid] - mx) * mask[b * S + tid] : 0.f;
    red[tid] = wgt; __syncthreads();
    for (int o = 128; o; o >>= 1) {
        if (tid < o) red[tid] += red[tid + o];
        __syncthreads();
    }
    const float inv = 1.f / red[0];
    if (tid < S) g_weight[b * S + tid] = wgt * inv;
}

// ---------------------------------------------------------------------------
// K4: att_res[b,d] = sum_s weight[b,s] * att_feats[b,s,d]
// ---------------------------------------------------------------------------
__global__ __launch_bounds__(256, 1) void k4_wsum(const float* __restrict__ feats,
                                                  float* __restrict__ out) {
    __shared__ float ws[S];
    const int b = blockIdx.x;
    const int dbase = blockIdx.y * 1024 + threadIdx.x * 4;

    if (threadIdx.x < S) ws[threadIdx.x] = g_weight[b * S + threadIdx.x];
    __syncthreads();

    const float4* fp = (const float4*)(feats + (size_t)b * S * D + dbase);
    float4 acc0 = make_float4(0.f, 0.f, 0.f, 0.f);
    float4 acc1 = make_float4(0.f, 0.f, 0.f, 0.f);
#pragma unroll 4
    for (int s = 0; s < S; s += 2) {
        float4 f0 = fp[(size_t)s * (D / 4)];
        float4 f1 = fp[(size_t)(s + 1) * (D / 4)];
        const float w0 = ws[s];
        const float w1 = ws[s + 1];
        acc0.x += w0 * f0.x; acc0.y += w0 * f0.y;
        acc0.z += w0 * f0.z; acc0.w += w0 * f0.w;
        acc1.x += w1 * f1.x; acc1.y += w1 * f1.y;
        acc1.z += w1 * f1.z; acc1.w += w1 * f1.w;
    }
    *(float4*)(out + (size_t)b * D + dbase) =
        make_float4(acc0.x + acc1.x, acc0.y + acc1.y,
                    acc0.z + acc1.z, acc0.w + acc1.w);
}

// ---------------------------------------------------------------------------
extern "C" void kernel_launch(void* const* d_in, const int* in_sizes, int n_in,
                              void* d_out, int out_size) {
    const float* h         = (const float*)d_in[0];   // [B,D]
    const float* att_feats = (const float*)d_in[1];   // [B,S,D]
    const float* p_att     = (const float*)d_in[2];   // [B,S,H]
    const float* mask      = (const float*)d_in[3];   // [B,S]
    const float* W         = (const float*)d_in[4];   // [H,D]
    const float* b_h2att   = (const float*)d_in[5];   // [H]
    const float* w_alpha   = (const float*)d_in[6];   // [H]
    // d_in[7] = b_alpha: cancels in softmax, unused.
    float* out = (float*)d_out;                        // [B,D]

    k0_convert<<<dim3(768 + 1536), 256>>>(h, W);
    k1_wmma   <<<dim3(2, 8, KSM), 256>>>();
    k2_fused  <<<dim3(B), 256>>>(p_att, w_alpha, b_h2att, mask);
    k4_wsum   <<<dim3(B, 2), 256>>>(att_feats, out);
}